// round 15
// baseline (speedup 1.0000x reference)
#include <cuda_runtime.h>
#include <cuda_bf16.h>

#define BATCH 8
#define CIN   256
#define CC    128
#define NPIX  2304
#define EPSB  1e-5f

// ---------------- scratch ------------------------------------------------------
__device__ __align__(16) float g_qt[BATCH*CC*NPIX];
__device__ __align__(16) float g_st[BATCH*CC*NPIX];
__device__ __align__(16) float g_kxT[BATCH*NPIX*CC];            // transposed tf32 key [b][n][c]
__device__ __align__(16) float g_qx[BATCH*CC*NPIX];             // tf32-rounded query
__device__ __align__(16) unsigned short g_vqh[BATCH*CC*NPIX];   // bf16 v_q
__device__ __align__(16) unsigned short g_vsh[BATCH*CC*NPIX];   // bf16 v_s
__device__ __align__(16) unsigned short g_e[(size_t)BATCH*NPIX*NPIX]; // bf16 exp(A-lm)
__device__ __align__(16) float g_cwr[CC*2304];                  // tf32-rounded conv w
__device__ float g_tmax[BATCH*18*18];
__device__ float g_rpart[BATCH*18*NPIX];   // [b][mblock][n] row partial sums
__device__ float g_cpart[BATCH*18*NPIX];   // [b][nblock][m] col partial sums
__device__ unsigned g_bmaxk[BATCH];
__device__ float g_poolq[BATCH*18*CC];
__device__ float g_pools[BATCH*18*CC];

// ---------------- helpers ------------------------------------------------------
__device__ __forceinline__ float tf(float x) {
    unsigned u;
    asm("cvt.rna.tf32.f32 %0, %1;" : "=r"(u) : "f"(x));
    return __uint_as_float(u);
}
__device__ __forceinline__ float4 tf4(float4 v) {
    v.x = tf(v.x); v.y = tf(v.y); v.z = tf(v.z); v.w = tf(v.w); return v;
}
__device__ __forceinline__ unsigned fkey(float x) {
    int i = __float_as_int(x);
    return (i >= 0) ? ((unsigned)i | 0x80000000u) : ~(unsigned)i;
}
__device__ __forceinline__ float fdekey(unsigned u) {
    int i = (u & 0x80000000u) ? (int)(u & 0x7fffffffu) : ~(int)u;
    return __int_as_float(i);
}
__device__ __forceinline__ unsigned packbf(float a, float b) {
    __nv_bfloat162 h = __floats2bfloat162_rn(a, b);
    return *(unsigned*)&h;
}
__device__ __forceinline__ int cpos(int j) { return ((j & 3) << 2) | (j >> 2); }

__device__ __forceinline__ void mma_tf32(float* c,
    unsigned a0, unsigned a1, unsigned a2, unsigned a3, unsigned b0, unsigned b1)
{
    asm volatile(
        "mma.sync.aligned.m16n8k8.row.col.f32.tf32.tf32.f32 "
        "{%0,%1,%2,%3}, {%4,%5,%6,%7}, {%8,%9}, {%0,%1,%2,%3};"
        : "+f"(c[0]), "+f"(c[1]), "+f"(c[2]), "+f"(c[3])
        : "r"(a0), "r"(a1), "r"(a2), "r"(a3), "r"(b0), "r"(b1));
}
__device__ __forceinline__ void mma_bf16(float* c,
    unsigned a0, unsigned a1, unsigned a2, unsigned a3, unsigned b0, unsigned b1)
{
    asm volatile(
        "mma.sync.aligned.m16n8k16.row.col.f32.bf16.bf16.f32 "
        "{%0,%1,%2,%3}, {%4,%5,%6,%7}, {%8,%9}, {%0,%1,%2,%3};"
        : "+f"(c[0]), "+f"(c[1]), "+f"(c[2]), "+f"(c[3])
        : "r"(a0), "r"(a1), "r"(a2), "r"(a3), "r"(b0), "r"(b1));
}

// ---- fp32/tf32 path, 256-thread: block 128x128x16, warp 64x32 -----------------
// A crosswise stride 20 (LDS.128 frags), B [k16][n+pad8]
__device__ __forceinline__ void mma_AB(float acc[4][4][4],
    const float* As, const float* Bs, int wm, int wn, int lane)
{
    const int gid = lane >> 2, t4 = lane & 3;
    const float4* As4 = (const float4*)As;
    float4 va[4][2];
#pragma unroll
    for (int mf = 0; mf < 4; ++mf) {
        int rb = wm*64 + mf*16 + gid;
        va[mf][0] = As4[rb*5 + t4];
        va[mf][1] = As4[(rb+8)*5 + t4];
    }
#pragma unroll
    for (int ko = 0; ko < 2; ++ko) {
        unsigned bf[4][2];
#pragma unroll
        for (int nf = 0; nf < 4; ++nf) {
            int nb = wn*32 + nf*8 + gid;
            bf[nf][0] = __float_as_uint(Bs[(ko*8+t4  )*136 + nb]);
            bf[nf][1] = __float_as_uint(Bs[(ko*8+t4+4)*136 + nb]);
        }
#pragma unroll
        for (int mf = 0; mf < 4; ++mf) {
            unsigned a0, a1, a2, a3;
            if (ko == 0) {
                a0 = __float_as_uint(va[mf][0].x); a1 = __float_as_uint(va[mf][1].x);
                a2 = __float_as_uint(va[mf][0].y); a3 = __float_as_uint(va[mf][1].y);
            } else {
                a0 = __float_as_uint(va[mf][0].z); a1 = __float_as_uint(va[mf][1].z);
                a2 = __float_as_uint(va[mf][0].w); a3 = __float_as_uint(va[mf][1].w);
            }
#pragma unroll
            for (int nf = 0; nf < 4; ++nf)
                mma_tf32(acc[mf][nf], a0, a1, a2, a3, bf[nf][0], bf[nf][1]);
        }
    }
}
// 512-thread variant: warp tile 32x32 (wm in 0..3)
__device__ __forceinline__ void mma_AB32(float acc[2][4][4],
    const float* As, const float* Bs, int wm, int wn, int lane)
{
    const int gid = lane >> 2, t4 = lane & 3;
    const float4* As4 = (const float4*)As;
    float4 va[2][2];
#pragma unroll
    for (int mf = 0; mf < 2; ++mf) {
        int rb = wm*32 + mf*16 + gid;
        va[mf][0] = As4[rb*5 + t4];
        va[mf][1] = As4[(rb+8)*5 + t4];
    }
#pragma unroll
    for (int ko = 0; ko < 2; ++ko) {
        unsigned bf[4][2];
#pragma unroll
        for (int nf = 0; nf < 4; ++nf) {
            int nb = wn*32 + nf*8 + gid;
            bf[nf][0] = __float_as_uint(Bs[(ko*8+t4  )*136 + nb]);
            bf[nf][1] = __float_as_uint(Bs[(ko*8+t4+4)*136 + nb]);
        }
#pragma unroll
        for (int mf = 0; mf < 2; ++mf) {
            unsigned a0, a1, a2, a3;
            if (ko == 0) {
                a0 = __float_as_uint(va[mf][0].x); a1 = __float_as_uint(va[mf][1].x);
                a2 = __float_as_uint(va[mf][0].y); a3 = __float_as_uint(va[mf][1].y);
            } else {
                a0 = __float_as_uint(va[mf][0].z); a1 = __float_as_uint(va[mf][1].z);
                a2 = __float_as_uint(va[mf][0].w); a3 = __float_as_uint(va[mf][1].w);
            }
#pragma unroll
            for (int nf = 0; nf < 4; ++nf)
                mma_tf32(acc[mf][nf], a0, a1, a2, a3, bf[nf][0], bf[nf][1]);
        }
    }
}
__device__ __forceinline__ void stA(float* As, int m, int aq, float4 v) {
    float* p = &As[m*20 + aq];
    p[0] = tf(v.x); p[4] = tf(v.y); p[8] = tf(v.z); p[12] = tf(v.w);
}
__device__ __forceinline__ void stAraw(float* As, int m, int aq, float4 v) {
    float* p = &As[m*20 + aq];
    p[0] = v.x; p[4] = v.y; p[8] = v.z; p[12] = v.w;
}

// ---- bf16 path: block 128x128x32, warp 64x32; A,B crosswise-uint stride 20 ----
__device__ __forceinline__ void mma_AB16(float acc[4][4][4],
    const unsigned* As, const unsigned* Bs, int wm, int wn, int lane)
{
    const int gid = lane >> 2, t4 = lane & 3;
    const uint4* A4 = (const uint4*)As;
    const uint4* B4 = (const uint4*)Bs;
    uint4 va[4][2], vb[4];
#pragma unroll
    for (int mf = 0; mf < 4; ++mf) {
        int rb = wm*64 + mf*16 + gid;
        va[mf][0] = A4[rb*5 + t4];
        va[mf][1] = A4[(rb+8)*5 + t4];
    }
#pragma unroll
    for (int nf = 0; nf < 4; ++nf) {
        int nb = wn*32 + nf*8 + gid;
        vb[nf] = B4[nb*5 + t4];
    }
#pragma unroll
    for (int mf = 0; mf < 4; ++mf)
#pragma unroll
        for (int nf = 0; nf < 4; ++nf)
            mma_bf16(acc[mf][nf], va[mf][0].x, va[mf][1].x, va[mf][0].y, va[mf][1].y,
                     vb[nf].x, vb[nf].y);
#pragma unroll
    for (int mf = 0; mf < 4; ++mf)
#pragma unroll
        for (int nf = 0; nf < 4; ++nf)
            mma_bf16(acc[mf][nf], va[mf][0].z, va[mf][1].z, va[mf][0].w, va[mf][1].w,
                     vb[nf].z, vb[nf].w);
}

#define ASZ (128*20)
#define BSZ (16*136)

// prep: round conv weights to tf32; block 0 also zeroes the batch-max keys
__global__ void prep_cw(const float* __restrict__ cw, float* __restrict__ cwr) {
    int i = blockIdx.x*256 + threadIdx.x;
    if (i < CC*2304) cwr[i] = tf(cw[i]);
    if (blockIdx.x == 0 && threadIdx.x < BATCH) g_bmaxk[threadIdx.x] = 0u;
}

// ---------------- batched 1x1 conv GEMM jobs ------------------------------------
// out  != 0 -> f32 [co][pix] (tf32-rounded iff tfr)
// outh != 0 -> bf16 [co][pix]
// outT != 0 -> tf32 f32 transposed [pix][co] via smem restage (coalesced)
struct GemmJob {
    const float* x; const float* w; const float* bias;
    const float* bng; const float* bnb; const float* bnm; const float* bnv;
    float* out; unsigned short* outh; float* outT; float* poolpart; int tfr;
};
struct GemmJobs { GemmJob j[4]; };

#define GPOOL (2*ASZ + 2*BSZ)   // 9472 floats; overlays T staging (64*132=8448)

__global__ __launch_bounds__(256, 2) void gemm_wx_t(GemmJobs jobs, int K)
{
    const GemmJob job = jobs.j[blockIdx.z];
    const int b  = blockIdx.y;
    const int p0 = blockIdx.x * 128;
    const float* xb = job.x + (size_t)b*K*NPIX;
    float* ob = job.out ? job.out + (size_t)b*CC*NPIX : 0;
    unsigned short* ohb = job.outh ? job.outh + (size_t)b*CC*NPIX : 0;
    float* otb = job.outT ? job.outT + (size_t)b*NPIX*CC : 0;
    const float* w = job.w;
    __shared__ __align__(16) float spool[GPOOL];
    float* As = spool;                 // [2][ASZ]
    float* Bs = spool + 2*ASZ;         // [2][BSZ]
    const int tid = threadIdx.x, lane = tid & 31, wid = tid >> 5;
    const int wm = wid & 1, wn = wid >> 1;
    const int gid = lane >> 2, t4 = lane & 3;
    const int am = tid >> 1, aq0 = 2*(tid & 1), aq1 = aq0 + 1;
    const int bk = tid >> 4, bq = tid & 15;
    float acc[4][4][4] = {};
    float4 pa0, pa1, pb0, pb1;
    pa0 = *(const float4*)&w[am*K + aq0*4];
    pa1 = *(const float4*)&w[am*K + aq1*4];
    pb0 = *(const float4*)&xb[(size_t)bk*NPIX + p0 + bq*4];
    pb1 = *(const float4*)&xb[(size_t)bk*NPIX + p0 + 64 + bq*4];
    stA(As, am, aq0, pa0); stA(As, am, aq1, pa1);
    *(float4*)&Bs[bk*136 + bq*4]      = tf4(pb0);
    *(float4*)&Bs[bk*136 + 64 + bq*4] = tf4(pb1);
    __syncthreads();
    const int iters = K / 16;
    for (int it = 0; it < iters; ++it) {
        if (it + 1 < iters) {
            int k0 = (it+1)*16;
            pa0 = *(const float4*)&w[am*K + k0 + aq0*4];
            pa1 = *(const float4*)&w[am*K + k0 + aq1*4];
            pb0 = *(const float4*)&xb[(size_t)(k0+bk)*NPIX + p0 + bq*4];
            pb1 = *(const float4*)&xb[(size_t)(k0+bk)*NPIX + p0 + 64 + bq*4];
        }
        mma_AB(acc, As + (it&1)*ASZ, Bs + (it&1)*BSZ, wm, wn, lane);
        if (it + 1 < iters) {
            int nb = (it+1) & 1;
            stA(As + nb*ASZ, am, aq0, pa0); stA(As + nb*ASZ, am, aq1, pa1);
            *(float4*)&Bs[nb*BSZ + bk*136 + bq*4]      = tf4(pb0);
            *(float4*)&Bs[nb*BSZ + bk*136 + 64 + bq*4] = tf4(pb1);
        }
        __syncthreads();
    }
    if (otb) {
        // transposed output: stage [pix][co] halves in smem, write coalesced
        float* T = spool;    // 64 x 132 floats
#pragma unroll
        for (int half2 = 0; half2 < 2; ++half2) {
            __syncthreads();
            if ((wn >> 1) == half2) {
#pragma unroll
                for (int mf = 0; mf < 4; ++mf)
#pragma unroll
                    for (int h = 0; h < 2; ++h) {
                        int o = wm*64 + mf*16 + gid + h*8;
                        float cb = job.bias[o];
#pragma unroll
                        for (int nf = 0; nf < 4; ++nf) {
                            int cl = wn*32 + nf*8 + t4*2 - half2*64;
                            T[(cl  )*132 + o] = tf(acc[mf][nf][2*h+0] + cb);
                            T[(cl+1)*132 + o] = tf(acc[mf][nf][2*h+1] + cb);
                        }
                    }
            }
            __syncthreads();
#pragma unroll
            for (int i = 0; i < 8; ++i) {
                int r = wid*8 + i;
                float4 v = *(const float4*)&T[r*132 + lane*4];
                *(float4*)&otb[(size_t)(p0 + half2*64 + r)*CC + lane*4] = v;
            }
        }
        return;
    }
    float rsum[8];
#pragma unroll
    for (int mf = 0; mf < 4; ++mf)
#pragma unroll
        for (int h = 0; h < 2; ++h) {
            int o = wm*64 + mf*16 + gid + h*8;
            float sc = 1.0f, cb = job.bias[o];
            if (job.bng) {
                sc = job.bng[o] * rsqrtf(job.bnv[o] + EPSB);
                cb = (job.bias[o] - job.bnm[o]) * sc + job.bnb[o];
            }
            float sm = 0.f;
#pragma unroll
            for (int nf = 0; nf < 4; ++nf) {
                int cl = wn*32 + nf*8 + t4*2;
                float2 r;
                r.x = acc[mf][nf][2*h+0]*sc + cb;
                r.y = acc[mf][nf][2*h+1]*sc + cb;
                sm += r.x + r.y;
                if (ohb) {
                    *(unsigned*)&ohb[(size_t)o*NPIX + p0 + cl] = packbf(r.x, r.y);
                } else {
                    if (job.tfr) { r.x = tf(r.x); r.y = tf(r.y); }
                    *(float2*)&ob[(size_t)o*NPIX + p0 + cl] = r;
                }
            }
            rsum[mf*2+h] = sm;
        }
    if (job.poolpart) {
        float* redp = spool;
        __syncthreads();
#pragma unroll
        for (int j = 0; j < 8; ++j) {
            float v = rsum[j];
            v += __shfl_xor_sync(~0u, v, 1);
            v += __shfl_xor_sync(~0u, v, 2);
            if (t4 == 0) {
                int row = wm*64 + (j>>1)*16 + gid + (j&1)*8;
                redp[wn*128 + row] = v;
            }
        }
        __syncthreads();
        if (tid < 128)
            job.poolpart[((size_t)b*18 + blockIdx.x)*CC + tid] =
                redp[tid] + redp[128+tid] + redp[256+tid] + redp[384+tid];
    }
}

// ---------------- score: crosswise A from kxT; coalesced e output ---------------
#define ESTRIDE 68
// mainloop: 2*ASZ + 2*BSZ = 9472 u32; epilogue: 128*68 + 512 + 16*132 = 11328 u32
#define POOLSZ (128*ESTRIDE + 512 + 16*132)

__global__ __launch_bounds__(256, 2) void score_t()
{
    const int b  = blockIdx.z;
    const int n0 = blockIdx.y * 128;
    const int m0 = blockIdx.x * 128;
    const float* kxT = g_kxT + ((size_t)b*NPIX + n0)*CC;
    const float* qx  = g_qx  + (size_t)b*CC*NPIX;
    unsigned short* eb = g_e + (size_t)b*NPIX*NPIX;
    __shared__ __align__(16) unsigned s_pool[POOLSZ];
    __shared__ float smax[8];
    float* Asf = (float*)s_pool;             // [2][ASZ] crosswise
    float* Bsf = Asf + 2*ASZ;                // [2][BSZ]
    const int tid = threadIdx.x, lane = tid & 31, wid = tid >> 5;
    const int wm = wid & 1, wn = wid >> 1;
    const int gid = lane >> 2, t4 = lane & 3;
    const int am = tid >> 1, aq0 = 2*(tid & 1), aq1 = aq0 + 1;
    const int bk = tid >> 4, bq = tid & 15;
    float acc[4][4][4] = {};
    float4 pa0, pa1, pb0, pb1;
    pa0 = *(const float4*)&kxT[(size_t)am*CC + aq0*4];
    pa1 = *(const float4*)&kxT[(size_t)am*CC + aq1*4];
    pb0 = *(const float4*)&qx[(size_t)bk*NPIX + m0 + bq*4];
    pb1 = *(const float4*)&qx[(size_t)bk*NPIX + m0 + 64 + bq*4];
    stAraw(Asf, am, aq0, pa0); stAraw(Asf, am, aq1, pa1);
    *(float4*)&Bsf[bk*136 + bq*4]      = pb0;
    *(float4*)&Bsf[bk*136 + 64 + bq*4] = pb1;
    __syncthreads();
    for (int it = 0; it < CC/16; ++it) {
        if (it + 1 < CC/16) {
            int k0 = (it+1)*16;
            pa0 = *(const float4*)&kxT[(size_t)am*CC + k0 + aq0*4];
            pa1 = *(const float4*)&kxT[(size_t)am*CC + k0 + aq1*4];
            pb0 = *(const float4*)&qx[(size_t)(k0+bk)*NPIX + m0 + bq*4];
            pb1 = *(const float4*)&qx[(size_t)(k0+bk)*NPIX + m0 + 64 + bq*4];
        }
        mma_AB(acc, Asf + (it&1)*ASZ, Bsf + (it&1)*BSZ, wm, wn, lane);
        if (it + 1 < CC/16) {
            int nb = (it+1) & 1;
            stAraw(Asf + nb*ASZ, am, aq0, pa0); stAraw(Asf + nb*ASZ, am, aq1, pa1);
            *(float4*)&Bsf[nb*BSZ + bk*136 + bq*4]      = pb0;
            *(float4*)&Bsf[nb*BSZ + bk*136 + 64 + bq*4] = pb1;
        }
        __syncthreads();
    }
    float mx = -1e30f;
#pragma unroll
    for (int mf = 0; mf < 4; ++mf)
#pragma unroll
        for (int nf = 0; nf < 4; ++nf)
#pragma unroll
            for (int v = 0; v < 4; ++v) mx = fmaxf(mx, acc[mf][nf][v]);
#pragma unroll
    for (int o = 16; o; o >>= 1) mx = fmaxf(mx, __shfl_xor_sync(~0u, mx, o));
    if (lane == 0) smax[wid] = mx;
    __syncthreads();
    float lm = smax[0];
#pragma unroll
    for (int j = 1; j < 8; ++j) lm = fmaxf(lm, smax[j]);
    unsigned* esh   = s_pool;                           // 128 x ESTRIDE uints
    float* rowred   = (float*)(s_pool + 128*ESTRIDE);   // 4 x 128
    float* colred   = rowred + 512;                     // 16 x 132
    float rowp[8] = {};
    float colp[8] = {};
#pragma unroll
    for (int mf = 0; mf < 4; ++mf)
#pragma unroll
        for (int h = 0; h < 2; ++h) {
            int nl = wm*64 + mf*16 + gid + h*8;
#pragma unroll
            for (int nf = 0; nf < 4; ++nf) {
                float e0 = __expf(acc[mf][nf][2*h+0] - lm);
                float e1 = __expf(acc[mf][nf][2*h+1] - lm);
                esh[nl*ESTRIDE + wn*16 + nf*4 + t4] = packbf(e0, e1);
                rowp[mf*2+h] += e0 + e1;
                colp[nf*2+0] += e0;
                colp[nf*2+1] += e1;
            }
        }
#pragma unroll
    for (int j = 0; j < 8; ++j) {
        float v = rowp[j];
        v += __shfl_xor_sync(~0u, v, 1);
        v += __shfl_xor_sync(~0u, v, 2);
        if (t4 == 0)
            rowred[wn*128 + wm*64 + (j>>1)*16 + gid + (j&1)*8] = v;
    }
#pragma unroll
    for (int j = 0; j < 8; ++j) {
        int cl = wn*32 + (j>>1)*8 + t4*2 + (j&1);
        colred[(wm*8+gid)*132 + cl] = colp[j];
    }
    __syncthreads();
#pragma unroll
    for (int i = 0; i < 16; ++i) {
        int r = wid*16 + i;
        uint2 v = *(const uint2*)&esh[r*ESTRIDE + lane*2];
        uint2* dst = (uint2*)(eb + (size_t)(n0 + r)*NPIX + m0);
        dst[lane] = v;
    }
    if (tid < 128) {
        float r = rowred[tid] + rowred[128+tid] + rowred[256+tid] + rowred[384+tid];
        g_rpart[((size_t)b*18 + blockIdx.x)*NPIX + n0 + tid] = r;
        float c = 0.f;
#pragma unroll
        for (int i = 0; i < 16; ++i) c += colred[i*132 + tid];
        g_cpart[((size_t)b*18 + blockIdx.y)*NPIX + m0 + tid] = c;
    }
    if (tid == 0) {
        g_tmax[(b*18 + blockIdx.y)*18 + blockIdx.x] = lm;
        atomicMax(&g_bmaxk[b], fkey(lm));
    }
}

// ---------------- merged attention (+inline gate): z=0 -> E_s, z=1 -> E_q -------
__global__ __launch_bounds__(256, 2) void attn_t(float* __restrict__ Es,
                                                 float* __restrict__ Eq,
    const float* __restrict__ gw1, const float* __restrict__ gb1,
    const float* __restrict__ gw2, const float* __restrict__ gb2)
{
    const int z  = blockIdx.z;
    const int b  = blockIdx.y;
    const int x0 = blockIdx.x * 128;       // n0 (z=0) or m0 (z=1)
    const unsigned short* eb = g_e + (size_t)b*NPIX*NPIX;
    const unsigned* vh = (const unsigned*)(z == 0 ? g_vsh : g_vqh)
                       + (size_t)b*CC*(NPIX/2);
    const float* resb = (z == 0 ? g_st : g_qt) + (size_t)b*CC*NPIX;
    const float* pp   = (z == 0 ? g_pools : g_poolq) + (size_t)b*18*CC;
    float* Eb = (z == 0 ? Es : Eq) + (size_t)b*CC*NPIX;
    __shared__ unsigned As[2][ASZ];
    __shared__ unsigned Bs[2][ASZ];
    __shared__ float tmx[18];
    __shared__ int   ordsh[18];
    __shared__ float ratio[18];
    __shared__ float inv_s[128];
    __shared__ float pool_sh[128];
    __shared__ float hsh[8];
    __shared__ float gate_sh[128];
    const int tid = threadIdx.x, lane = tid & 31, wid = tid >> 5;
    const int wm = wid & 1, wn = wid >> 1;
    const int gid = lane >> 2, t4 = lane & 3;
    const int am = tid >> 1, half = tid & 1;
    const float bmax = fdekey(g_bmaxk[b]);
    if (tid < 18)
        tmx[tid] = (z == 0) ? g_tmax[(b*18 + blockIdx.x)*18 + tid]
                            : g_tmax[(b*18 + tid)*18 + blockIdx.x];
    if (tid >= 64 && tid < 192) {
        int i = tid - 64;
        float s = 0.f;
#pragma unroll
        for (int j = 0; j < 18; ++j) s += pp[j*CC + i];
        pool_sh[i] = s * (1.0f/NPIX);
    }
    __syncthreads();
    if (tid < 18) {
        float mine = tmx[tid];
        int rank = 0;
        for (int j = 0; j < 18; ++j) {
            float o = tmx[j];
            rank += (o < mine) || (o == mine && j < tid);
        }
        ordsh[rank] = tid;
    }
    if (tid >= 32 && tid < 64) {
        int l = tid - 32;
        int j = l & 7, seg = l >> 3;
        float h = 0.f;
#pragma unroll
        for (int i = 0; i < 32; ++i)
            h += pool_sh[seg*32 + i] * gw1[j*CC + seg*32 + i];
        h += __shfl_xor_sync(0xffffffffu, h, 8);
        h += __shfl_xor_sync(0xffffffffu, h, 16);
        if (l < 8) hsh[j] = fmaxf(h + gb1[j], 0.f);
    }
    __syncthreads();
    if (tid < 18)
        ratio[tid] = (tid == 0) ? 1.0f : __expf(tmx[ordsh[tid-1]] - tmx[ordsh[tid]]);
    if (tid >= 32 && tid < 160) {
        int i = tid - 32;
        const float* part = (z == 0 ? g_rpart : g_cpart);
        float s = 0.f;
#pragma unroll
        for (int t = 0; t < 18; ++t)
            s += __expf(tmx[t] - bmax) * part[((size_t)b*18 + t)*NPIX + x0 + i];
        inv_s[i] = s;
    }
    if (tid >= 192) {
        int i0 = (tid - 192)*2;
#pragma unroll
        for (int u = 0; u < 2; ++u) {
            int i = i0 + u;
            float zv = gb2[i];
#pragma unroll
            for (int j = 0; j < 8; ++j) zv += hsh[j] * gw2[i*8 + j];
            gate_sh[i] = 1.0f / (1.0f + __expf(-zv));
        }
    }
    __syncthreads();
    if (tid < 128) {
        float slast = __expf(tmx[ordsh[17]] - bmax);
        inv_s[tid] = slast / inv_s[tid];
    }
    float acc[4][4][4] = {};
    const unsigned* arow = vh + (size_t)am*(NPIX/2) + half*8;

    if (z == 0) {
        const unsigned* erow = (const unsigned*)(eb + (size_t)(x0+am)*NPIX) + half*8;
        uint4 pa0, pa1, pb0, pb1;
        {
            int ko2 = ordsh[0]*64;
            pa0 = *(const uint4*)&arow[ko2];  pa1 = *(const uint4*)&arow[ko2+4];
            pb0 = *(const uint4*)&erow[ko2];  pb1 = *(const uint4*)&erow[ko2+4];
        }
        auto store = [&](int buf) {
            unsigned* Ap = &As[buf][am*20];
            unsigned* Bp = &Bs[buf][am*20];
            unsigned ua[8] = {pa0.x,pa0.y,pa0.z,pa0.w, pa1.x,pa1.y,pa1.z,pa1.w};
            unsigned ub[8] = {pb0.x,pb0.y,pb0.z,pb0.w, pb1.x,pb1.y,pb1.z,pb1.w};
#pragma unroll
            for (int i = 0; i < 8; ++i) {
                int c = cpos(half*8 + i);
                Ap[c] = ua[i];
                Bp[c] = ub[i];
            }
        };
        store(0);
        __syncthreads();
        for (int it = 0; it < 72; ++it) {
            if (it + 1 < 72) {
                int nit = it + 1;
                int ko2 = ordsh[nit>>2]*64 + (nit&3)*16;
                pa0 = *(const uint4*)&arow[ko2];  pa1 = *(const uint4*)&arow[ko2+4];
                pb0 = *(const uint4*)&erow[ko2];  pb1 = *(const uint4*)&erow[ko2+4];
            }
            if ((it & 3) == 0 && it) {
                float r = ratio[it>>2];
#pragma unroll
                for (int mf = 0; mf < 4; ++mf)
#pragma unroll
                    for (int nf = 0; nf < 4; ++nf)
#pragma unroll
                        for (int v = 0; v < 4; ++v) acc[mf][nf][v] *= r;
            }
            mma_AB16(acc, As[it & 1], Bs[it & 1], wm, wn, lane);
            if (it + 1 < 72) store((it+1) & 1);
            __syncthreads();
        }
    } else {
        const int np = tid >> 4, mseg = tid & 15;
        const unsigned* ebase = (const unsigned*)eb + x0/2 + mseg*4;
        const int ppos = cpos(np);
        uint4 pa0, pa1, pb0, pb1;
        {
            int k0 = ordsh[0]*128;
            pa0 = *(const uint4*)&arow[ordsh[0]*64];
            pa1 = *(const uint4*)&arow[ordsh[0]*64 + 4];
            pb0 = *(const uint4*)&ebase[(size_t)(k0 + 2*np    )*(NPIX/2)];
            pb1 = *(const uint4*)&ebase[(size_t)(k0 + 2*np + 1)*(NPIX/2)];
        }
        auto store = [&](int buf) {
            unsigned* Ap = &As[buf][am*20];
            unsigned ua[8] = {pa0.x,pa0.y,pa0.z,pa0.w, pa1.x,pa1.y,pa1.z,pa1.w};
#pragma unroll
            for (int i = 0; i < 8; ++i) Ap[cpos(half*8 + i)] = ua[i];
            unsigned u0[4] = {pb0.x, pb0.y, pb0.z, pb0.w};
            unsigned u1[4] = {pb1.x, pb1.y, pb1.z, pb1.w};
#pragma unroll
            for (int jj = 0; jj < 4; ++jj) {
                unsigned q0 = __byte_perm(u0[jj], u1[jj], 0x5410);
                unsigned q1 = __byte_perm(u0[jj], u1[jj], 0x7632);
                int ml = mseg*8 + 2*jj;
                Bs[buf][ml*20 + ppos]     = q0;
                Bs[buf][(ml+1)*20 + ppos] = q1;
            }
        };
        store(0);
        __syncthreads();
        for (int it = 0; it < 72; ++it) {
            if (it + 1 < 72) {
                int nit = it + 1;
                int kt = ordsh[nit>>2];
                int k0 = kt*128 + (nit&3)*32;
                pa0 = *(const uint4*)&arow[kt*64 + (nit&3)*16];
                pa1 = *(const uint4*)&arow[kt*64 + (nit&3)*16 + 4];
                pb0 = *(const uint4*)&ebase[(size_t)(k0 + 2*np    )*(NPIX/2)];
                pb1 = *(const uint4*)&ebase[(size_t)(k0 + 2*np + 1)*(NPIX/2)];
            }
            if ((it & 3) == 0 && it) {
                float r = ratio[it>>2];
#pragma unroll
                for (int mf = 0; mf < 4; ++mf)
#pragma unroll
                    for (int nf = 0; nf < 4; ++nf)
#pragma unroll
                        for (int v = 0; v < 4; ++v) acc[mf][nf][v] *= r;
            }
            mma_AB16(acc, As[it & 1], Bs[it & 1], wm, wn, lane);
            if (it + 1 < 72) store((it+1) & 1);
            __syncthreads();
        }
    }
#pragma unroll
    for (int mf = 0; mf < 4; ++mf)
#pragma unroll
        for (int h = 0; h < 2; ++h) {
            int co = wm*64 + mf*16 + gid + h*8;
            float g = gate_sh[co];
#pragma unroll
            for (int nf = 0; nf < 4; ++nf) {
                int cl = wn*32 + nf*8 + t4*2;
                float2 res = *(const float2*)&resb[(size_t)co*NPIX + x0 + cl];
                float2 r;
                r.x = g*acc[mf][nf][2*h+0]*inv_s[cl]   + res.x;
                r.y = g*acc[mf][nf][2*h+1]*inv_s[cl+1] + res.y;
                *(float2*)&Eb[(size_t)co*NPIX + x0 + cl] = r;
            }
        }
}

// ---------------- 3x3 conv: 512 threads, warp tile 32x32, tf32 ------------------
__global__ __launch_bounds__(512) void conv_t(
    const float* __restrict__ cwr, const float* __restrict__ cg,
    const float* __restrict__ cb, const float* __restrict__ cm,
    const float* __restrict__ cv,
    const float* __restrict__ Eq, const float* __restrict__ Es,
    float* __restrict__ feat)
{
    const int b  = blockIdx.y;
    const int p0 = blockIdx.x * 128;
    const float* Eqb = Eq + (size_t)b*CC*NPIX;
    const float* Esb = Es + (size_t)b*CC*NPIX;
    float* fb = feat + (size_t)b*CC*NPIX;
    __shared__ __align__(16) float As[2][ASZ];
    __shared__ __align__(16) float Bs[2][BSZ];
    const int tid = threadIdx.x, lane = tid & 31, wid = tid >> 5;
    const int wm = wid & 3, wn = wid >> 2;           // 4 x 4 warps
    const int gid = lane >> 2, t4 = lane & 3;
    const int am = tid >> 2, aq = tid & 3;           // A: 1 float4 / thread
    const int bk = tid >> 5, bq = tid & 31;          // B: 4 pixels / thread
    int hh[4], ww[4];
#pragma unroll
    for (int j = 0; j < 4; ++j) {
        int p = p0 + bq*4 + j;
        hh[j] = p / 48; ww[j] = p - hh[j]*48;
    }
    auto loadB = [&](int k0, float4& v) {
        int kap = k0 + bk;
        int ic = kap / 9, kk = kap - ic*9;
        int dh = kk/3 - 1, dw = kk - (kk/3)*3 - 1;
        const float* src = (ic < CC) ? Eqb : Esb;
        const float* sp = src + (size_t)(ic & (CC-1))*NPIX;
        float* vp = (float*)&v;
#pragma unroll
        for (int j = 0; j < 4; ++j) {
            int ih = hh[j] + dh, iw = ww[j] + dw;
            vp[j] = ((unsigned)ih < 48u && (unsigned)iw < 48u)
                  ? sp[ih*48 + iw] : 0.f;
        }
    };
    float acc[2][4][4] = {};
    float4 pa, pb;
    pa = *(const float4*)&cwr[am*2304 + aq*4];
    loadB(0, pb);
    stAraw(As[0], am, aq, pa);
    *(float4*)&Bs[0][bk*136 + bq*4] = tf4(pb);
    __syncthreads();
    for (int it = 0; it < 144; ++it) {
        if (it + 1 < 144) {
            int k0 = (it+1)*16;
            pa = *(const float4*)&cwr[am*2304 + k0 + aq*4];
            loadB(k0, pb);
        }
        mma_AB32(acc, As[it & 1], Bs[it & 1], wm, wn, lane);
        if (it + 1 < 144) {
            int nb = (it+1) & 1;
            stAraw(As[nb], am, aq, pa);
            *(float4*)&Bs[nb][bk*136 + bq*4] = tf4(pb);
        }
        __syncthreads();
    }
#pragma unroll
    for (int mf = 0; mf < 2; ++mf)
#pragma unroll
        for (int h = 0; h < 2; ++h) {
            int o = wm*32 + mf*16 + gid + h*8;
            float sc  = cg[o] * rsqrtf(cv[o] + EPSB);
            float cbv = cb[o] - cm[o]*sc;
#pragma unroll
            for (int nf = 0; nf < 4; ++nf) {
                int cl = wn*32 + nf*8 + t4*2;
                float2 r;
                r.x = fmaxf(acc[mf][nf][2*h+0]*sc + cbv, 0.f);
                r.y = fmaxf(acc[mf][nf][2*h+1]*sc + cbv, 0.f);
                *(float2*)&fb[(size_t)o*NPIX + p0 + cl] = r;
            }
        }
}

// ---------------- host ----------------------------------------------------------
extern "C" void kernel_launch(void* const* d_in, const int* in_sizes, int n_in,
                              void* d_out, int out_size)
{
    (void)in_sizes; (void)n_in; (void)out_size;
    const float* q    = (const float*)d_in[0];
    const float* s    = (const float*)d_in[1];
    const float* tsw  = (const float*)d_in[2];
    const float* tsb  = (const float*)d_in[3];
    const float* bsg  = (const float*)d_in[4];
    const float* bsb  = (const float*)d_in[5];
    const float* bsm  = (const float*)d_in[6];
    const float* bsv  = (const float*)d_in[7];
    const float* tqw  = (const float*)d_in[8];
    const float* tqb  = (const float*)d_in[9];
    const float* bqg  = (const float*)d_in[10];
    const float* bqb  = (const float*)d_in[11];
    const float* bqm  = (const float*)d_in[12];
    const float* bqv  = (const float*)d_in[13];
    const float* vqw  = (const float*)d_in[14];
    const float* vqb  = (const float*)d_in[15];
    const float* vsw  = (const float*)d_in[16];
    const float* vsb  = (const float*)d_in[17];
    const float* keyw = (const float*)d_in[18];
    const float* keyb = (const float*)d_in[19];
    const float* qryw = (const float*)d_in[20];
    const float* qryb = (const float*)d_in[21];
    const float* gw1  = (const float*)d_in[22];
    const float* gb1  = (const float*)d_in[23];
    const float* gw2  = (const float*)d_in[24];
    const float* gb2  = (const float*)d_in[25];
    const float* cw   = (const float*)d_in[26];
    const float* cg   = (const float*)d_in[27];
    const float* cb   = (const float*)d_in[28];
    const float* cm   = (const float*)d_in[29];
    const float* cv   = (const float*)d_in[30];

    float *p_qt, *p_st, *p_kxT, *p_qx, *p_pq, *p_ps, *p_cwr;
    unsigned short *p_vqh, *p_vsh;
    cudaGetSymbolAddress((void**)&p_qt,  g_qt);
    cudaGetSymbolAddress((void**)&p_st,  g_st);
    cudaGetSymbolAddress((void**)&p_kxT, g_kxT);
    cudaGetSymbolAddress((void**)&p_qx,  g_qx);
    cudaGetSymbolAddress((void**)&p_pq,  g_poolq);
    cudaGetSymbolAddress((void**)&p_ps,  g_pools);
    cudaGetSymbolAddress((void**)&p_cwr, g_cwr);
    cudaGetSymbolAddress((void**)&p_vqh, g_vqh);
    cudaGetSymbolAddress((void**)&p_vsh, g_vsh);

    float* feat = (float*)d_out;
    float* Eq   = feat + (size_t)BATCH*CC*NPIX;
    float* Es   = Eq   + (size_t)BATCH*CC*NPIX;

    prep_cw<<<1152, 256>>>(cw, p_cwr);

    // trans pair: z=0 -> q', z=1 -> s'
    {
        GemmJobs jt = {};
        jt.j[0] = { q, tqw, tqb, bqg, bqb, bqm, bqv, p_qt, 0, 0, p_pq, 0 };
        jt.j[1] = { s, tsw, tsb, bsg, bsb, bsm, bsv, p_st, 0, 0, p_ps, 0 };
        gemm_wx_t<<<dim3(18, BATCH, 2), 256>>>(jt, CIN);
    }
    // projection quad: v_q(bf16), q_x(tf32), v_s(bf16), k_x(transposed tf32)
    {
        GemmJobs jp = {};
        jp.j[0] = { p_qt, vqw,  vqb,  0, 0, 0, 0, 0,    p_vqh, 0,     0, 0 };
        jp.j[1] = { p_qt, qryw, qryb, 0, 0, 0, 0, p_qx, 0,     0,     0, 1 };
        jp.j[2] = { p_st, vsw,  vsb,  0, 0, 0, 0, 0,    p_vsh, 0,     0, 0 };
        jp.j[3] = { p_st, keyw, keyb, 0, 0, 0, 0, 0,    0,     p_kxT, 0, 0 };
        gemm_wx_t<<<dim3(18, BATCH, 4), 256>>>(jp, CC);
    }

    score_t<<<dim3(18, 18, BATCH), 256>>>();

    attn_t<<<dim3(18, BATCH, 2), 256>>>(Es, Eq, gw1, gb1, gw2, gb2);

    conv_t<<<dim3(18, BATCH), 512>>>(p_cwr, cg, cb, cm, cv, Eq, Es, feat);
}

// round 17
// speedup vs baseline: 1.0635x; 1.0635x over previous
#include <cuda_runtime.h>
#include <cuda_bf16.h>

#define BATCH 8
#define CIN   256
#define CC    128
#define NPIX  2304
#define EPSB  1e-5f

// ---------------- scratch ------------------------------------------------------
__device__ __align__(16) float g_qt[BATCH*CC*NPIX];
__device__ __align__(16) float g_st[BATCH*CC*NPIX];
__device__ __align__(16) float g_kx[BATCH*CC*NPIX];             // tf32-rounded key
__device__ __align__(16) float g_qx[BATCH*CC*NPIX];             // tf32-rounded query
__device__ __align__(16) unsigned short g_vqh[BATCH*CC*NPIX];   // bf16 v_q
__device__ __align__(16) unsigned short g_vsh[BATCH*CC*NPIX];   // bf16 v_s
__device__ __align__(16) unsigned short g_e[(size_t)BATCH*NPIX*NPIX]; // bf16 exp(A-lm)
__device__ __align__(16) float g_cwr[CC*2304];                  // tf32-rounded conv w
__device__ float g_tmax[BATCH*18*18];
__device__ float g_rpart[BATCH*18*NPIX];   // [b][mblock][n] row partial sums
__device__ float g_cpart[BATCH*18*NPIX];   // [b][nblock][m] col partial sums
__device__ unsigned g_bmaxk[BATCH];
__device__ float g_poolq[BATCH*18*CC];
__device__ float g_pools[BATCH*18*CC];

// ---------------- helpers ------------------------------------------------------
__device__ __forceinline__ float tf(float x) {
    unsigned u;
    asm("cvt.rna.tf32.f32 %0, %1;" : "=r"(u) : "f"(x));
    return __uint_as_float(u);
}
__device__ __forceinline__ float4 tf4(float4 v) {
    v.x = tf(v.x); v.y = tf(v.y); v.z = tf(v.z); v.w = tf(v.w); return v;
}
__device__ __forceinline__ unsigned fkey(float x) {
    int i = __float_as_int(x);
    return (i >= 0) ? ((unsigned)i | 0x80000000u) : ~(unsigned)i;
}
__device__ __forceinline__ float fdekey(unsigned u) {
    int i = (u & 0x80000000u) ? (int)(u & 0x7fffffffu) : ~(int)u;
    return __int_as_float(i);
}
__device__ __forceinline__ unsigned packbf(float a, float b) {
    __nv_bfloat162 h = __floats2bfloat162_rn(a, b);
    return *(unsigned*)&h;
}
__device__ __forceinline__ int cpos(int j) { return ((j & 3) << 2) | (j >> 2); }

__device__ __forceinline__ void mma_tf32(float* c,
    unsigned a0, unsigned a1, unsigned a2, unsigned a3, unsigned b0, unsigned b1)
{
    asm volatile(
        "mma.sync.aligned.m16n8k8.row.col.f32.tf32.tf32.f32 "
        "{%0,%1,%2,%3}, {%4,%5,%6,%7}, {%8,%9}, {%0,%1,%2,%3};"
        : "+f"(c[0]), "+f"(c[1]), "+f"(c[2]), "+f"(c[3])
        : "r"(a0), "r"(a1), "r"(a2), "r"(a3), "r"(b0), "r"(b1));
}
__device__ __forceinline__ void mma_bf16(float* c,
    unsigned a0, unsigned a1, unsigned a2, unsigned a3, unsigned b0, unsigned b1)
{
    asm volatile(
        "mma.sync.aligned.m16n8k16.row.col.f32.bf16.bf16.f32 "
        "{%0,%1,%2,%3}, {%4,%5,%6,%7}, {%8,%9}, {%0,%1,%2,%3};"
        : "+f"(c[0]), "+f"(c[1]), "+f"(c[2]), "+f"(c[3])
        : "r"(a0), "r"(a1), "r"(a2), "r"(a3), "r"(b0), "r"(b1));
}

// ---- fp32/tf32 path, 256-thread: block 128x128x16, warp 64x32 -----------------
__device__ __forceinline__ void mma_AB(float acc[4][4][4],
    const float* As, const float* Bs, int wm, int wn, int lane)
{
    const int gid = lane >> 2, t4 = lane & 3;
    const float4* As4 = (const float4*)As;
    float4 va[4][2];
#pragma unroll
    for (int mf = 0; mf < 4; ++mf) {
        int rb = wm*64 + mf*16 + gid;
        va[mf][0] = As4[rb*5 + t4];
        va[mf][1] = As4[(rb+8)*5 + t4];
    }
#pragma unroll
    for (int ko = 0; ko < 2; ++ko) {
        unsigned bf[4][2];
#pragma unroll
        for (int nf = 0; nf < 4; ++nf) {
            int nb = wn*32 + nf*8 + gid;
            bf[nf][0] = __float_as_uint(Bs[(ko*8+t4  )*136 + nb]);
            bf[nf][1] = __float_as_uint(Bs[(ko*8+t4+4)*136 + nb]);
        }
#pragma unroll
        for (int mf = 0; mf < 4; ++mf) {
            unsigned a0, a1, a2, a3;
            if (ko == 0) {
                a0 = __float_as_uint(va[mf][0].x); a1 = __float_as_uint(va[mf][1].x);
                a2 = __float_as_uint(va[mf][0].y); a3 = __float_as_uint(va[mf][1].y);
            } else {
                a0 = __float_as_uint(va[mf][0].z); a1 = __float_as_uint(va[mf][1].z);
                a2 = __float_as_uint(va[mf][0].w); a3 = __float_as_uint(va[mf][1].w);
            }
#pragma unroll
            for (int nf = 0; nf < 4; ++nf)
                mma_tf32(acc[mf][nf], a0, a1, a2, a3, bf[nf][0], bf[nf][1]);
        }
    }
}
// score variant: A also in [k][n+pad] layout (scalar a-frag loads)
__device__ __forceinline__ void mma_AB_kn(float acc[4][4][4],
    const float* As, const float* Bs, int wm, int wn, int lane)
{
    const int gid = lane >> 2, t4 = lane & 3;
#pragma unroll
    for (int ko = 0; ko < 2; ++ko) {
        unsigned bf[4][2];
#pragma unroll
        for (int nf = 0; nf < 4; ++nf) {
            int nb = wn*32 + nf*8 + gid;
            bf[nf][0] = __float_as_uint(Bs[(ko*8+t4  )*136 + nb]);
            bf[nf][1] = __float_as_uint(Bs[(ko*8+t4+4)*136 + nb]);
        }
#pragma unroll
        for (int mf = 0; mf < 4; ++mf) {
            int rb = wm*64 + mf*16 + gid;
            unsigned a0 = __float_as_uint(As[(ko*8+t4  )*136 + rb]);
            unsigned a1 = __float_as_uint(As[(ko*8+t4  )*136 + rb+8]);
            unsigned a2 = __float_as_uint(As[(ko*8+t4+4)*136 + rb]);
            unsigned a3 = __float_as_uint(As[(ko*8+t4+4)*136 + rb+8]);
#pragma unroll
            for (int nf = 0; nf < 4; ++nf)
                mma_tf32(acc[mf][nf], a0, a1, a2, a3, bf[nf][0], bf[nf][1]);
        }
    }
}
// 512-thread variant: warp tile 32x32 (wm in 0..3)
__device__ __forceinline__ void mma_AB32(float acc[2][4][4],
    const float* As, const float* Bs, int wm, int wn, int lane)
{
    const int gid = lane >> 2, t4 = lane & 3;
    const float4* As4 = (const float4*)As;
    float4 va[2][2];
#pragma unroll
    for (int mf = 0; mf < 2; ++mf) {
        int rb = wm*32 + mf*16 + gid;
        va[mf][0] = As4[rb*5 + t4];
        va[mf][1] = As4[(rb+8)*5 + t4];
    }
#pragma unroll
    for (int ko = 0; ko < 2; ++ko) {
        unsigned bf[4][2];
#pragma unroll
        for (int nf = 0; nf < 4; ++nf) {
            int nb = wn*32 + nf*8 + gid;
            bf[nf][0] = __float_as_uint(Bs[(ko*8+t4  )*136 + nb]);
            bf[nf][1] = __float_as_uint(Bs[(ko*8+t4+4)*136 + nb]);
        }
#pragma unroll
        for (int mf = 0; mf < 2; ++mf) {
            unsigned a0, a1, a2, a3;
            if (ko == 0) {
                a0 = __float_as_uint(va[mf][0].x); a1 = __float_as_uint(va[mf][1].x);
                a2 = __float_as_uint(va[mf][0].y); a3 = __float_as_uint(va[mf][1].y);
            } else {
                a0 = __float_as_uint(va[mf][0].z); a1 = __float_as_uint(va[mf][1].z);
                a2 = __float_as_uint(va[mf][0].w); a3 = __float_as_uint(va[mf][1].w);
            }
#pragma unroll
            for (int nf = 0; nf < 4; ++nf)
                mma_tf32(acc[mf][nf], a0, a1, a2, a3, bf[nf][0], bf[nf][1]);
        }
    }
}
__device__ __forceinline__ void stA(float* As, int m, int aq, float4 v) {
    float* p = &As[m*20 + aq];
    p[0] = tf(v.x); p[4] = tf(v.y); p[8] = tf(v.z); p[12] = tf(v.w);
}
__device__ __forceinline__ void stAraw(float* As, int m, int aq, float4 v) {
    float* p = &As[m*20 + aq];
    p[0] = v.x; p[4] = v.y; p[8] = v.z; p[12] = v.w;
}

// ---- bf16 path: block 128x128x32, warp 64x32; A,B crosswise-uint stride 20 ----
__device__ __forceinline__ void mma_AB16(float acc[4][4][4],
    const unsigned* As, const unsigned* Bs, int wm, int wn, int lane)
{
    const int gid = lane >> 2, t4 = lane & 3;
    const uint4* A4 = (const uint4*)As;
    const uint4* B4 = (const uint4*)Bs;
    uint4 va[4][2], vb[4];
#pragma unroll
    for (int mf = 0; mf < 4; ++mf) {
        int rb = wm*64 + mf*16 + gid;
        va[mf][0] = A4[rb*5 + t4];
        va[mf][1] = A4[(rb+8)*5 + t4];
    }
#pragma unroll
    for (int nf = 0; nf < 4; ++nf) {
        int nb = wn*32 + nf*8 + gid;
        vb[nf] = B4[nb*5 + t4];
    }
#pragma unroll
    for (int mf = 0; mf < 4; ++mf)
#pragma unroll
        for (int nf = 0; nf < 4; ++nf)
            mma_bf16(acc[mf][nf], va[mf][0].x, va[mf][1].x, va[mf][0].y, va[mf][1].y,
                     vb[nf].x, vb[nf].y);
#pragma unroll
    for (int mf = 0; mf < 4; ++mf)
#pragma unroll
        for (int nf = 0; nf < 4; ++nf)
            mma_bf16(acc[mf][nf], va[mf][0].z, va[mf][1].z, va[mf][0].w, va[mf][1].w,
                     vb[nf].z, vb[nf].w);
}

#define ASZ (128*20)
#define BSZ (16*136)

// prep: round conv weights to tf32; block 0 also zeroes the batch-max keys
__global__ void prep_cw(const float* __restrict__ cw, float* __restrict__ cwr) {
    int i = blockIdx.x*256 + threadIdx.x;
    if (i < CC*2304) cwr[i] = tf(cw[i]);
    if (blockIdx.x == 0 && threadIdx.x < BATCH) g_bmaxk[threadIdx.x] = 0u;
}

// ---------------- batched 1x1 conv GEMM jobs ------------------------------------
struct GemmJob {
    const float* x; const float* w; const float* bias;
    const float* bng; const float* bnb; const float* bnm; const float* bnv;
    float* out; unsigned short* outh; float* poolpart; int tfr;
};
struct GemmJobs { GemmJob j[4]; };

__global__ __launch_bounds__(256, 2) void gemm_wx_t(GemmJobs jobs, int K)
{
    const GemmJob job = jobs.j[blockIdx.z];
    const int b  = blockIdx.y;
    const int p0 = blockIdx.x * 128;
    const float* xb = job.x + (size_t)b*K*NPIX;
    float* ob = job.out ? job.out + (size_t)b*CC*NPIX : 0;
    unsigned short* ohb = job.outh ? job.outh + (size_t)b*CC*NPIX : 0;
    const float* w = job.w;
    __shared__ __align__(16) float As[2][ASZ];
    __shared__ __align__(16) float Bs[2][BSZ];
    const int tid = threadIdx.x, lane = tid & 31, wid = tid >> 5;
    const int wm = wid & 1, wn = wid >> 1;
    const int gid = lane >> 2, t4 = lane & 3;
    const int am = tid >> 1, aq0 = 2*(tid & 1), aq1 = aq0 + 1;
    const int bk = tid >> 4, bq = tid & 15;
    float acc[4][4][4] = {};
    float4 pa0, pa1, pb0, pb1;
    pa0 = *(const float4*)&w[am*K + aq0*4];
    pa1 = *(const float4*)&w[am*K + aq1*4];
    pb0 = *(const float4*)&xb[(size_t)bk*NPIX + p0 + bq*4];
    pb1 = *(const float4*)&xb[(size_t)bk*NPIX + p0 + 64 + bq*4];
    stA(As[0], am, aq0, pa0); stA(As[0], am, aq1, pa1);
    *(float4*)&Bs[0][bk*136 + bq*4]      = tf4(pb0);
    *(float4*)&Bs[0][bk*136 + 64 + bq*4] = tf4(pb1);
    __syncthreads();
    const int iters = K / 16;
    for (int it = 0; it < iters; ++it) {
        if (it + 1 < iters) {
            int k0 = (it+1)*16;
            pa0 = *(const float4*)&w[am*K + k0 + aq0*4];
            pa1 = *(const float4*)&w[am*K + k0 + aq1*4];
            pb0 = *(const float4*)&xb[(size_t)(k0+bk)*NPIX + p0 + bq*4];
            pb1 = *(const float4*)&xb[(size_t)(k0+bk)*NPIX + p0 + 64 + bq*4];
        }
        mma_AB(acc, As[it & 1], Bs[it & 1], wm, wn, lane);
        if (it + 1 < iters) {
            int nb = (it+1) & 1;
            stA(As[nb], am, aq0, pa0); stA(As[nb], am, aq1, pa1);
            *(float4*)&Bs[nb][bk*136 + bq*4]      = tf4(pb0);
            *(float4*)&Bs[nb][bk*136 + 64 + bq*4] = tf4(pb1);
        }
        __syncthreads();
    }
    float rsum[8];
#pragma unroll
    for (int mf = 0; mf < 4; ++mf)
#pragma unroll
        for (int h = 0; h < 2; ++h) {
            int o = wm*64 + mf*16 + gid + h*8;
            float sc = 1.0f, cb = job.bias[o];
            if (job.bng) {
                sc = job.bng[o] * rsqrtf(job.bnv[o] + EPSB);
                cb = (job.bias[o] - job.bnm[o]) * sc + job.bnb[o];
            }
            float sm = 0.f;
#pragma unroll
            for (int nf = 0; nf < 4; ++nf) {
                int cl = wn*32 + nf*8 + t4*2;
                float2 r;
                r.x = acc[mf][nf][2*h+0]*sc + cb;
                r.y = acc[mf][nf][2*h+1]*sc + cb;
                sm += r.x + r.y;
                if (ohb) {
                    *(unsigned*)&ohb[(size_t)o*NPIX + p0 + cl] = packbf(r.x, r.y);
                } else {
                    if (job.tfr) { r.x = tf(r.x); r.y = tf(r.y); }
                    *(float2*)&ob[(size_t)o*NPIX + p0 + cl] = r;
                }
            }
            rsum[mf*2+h] = sm;
        }
    if (job.poolpart) {
        float* redp = (float*)As;
        __syncthreads();
#pragma unroll
        for (int j = 0; j < 8; ++j) {
            float v = rsum[j];
            v += __shfl_xor_sync(~0u, v, 1);
            v += __shfl_xor_sync(~0u, v, 2);
            if (t4 == 0) {
                int row = wm*64 + (j>>1)*16 + gid + (j&1)*8;
                redp[wn*128 + row] = v;
            }
        }
        __syncthreads();
        if (tid < 128)
            job.poolpart[((size_t)b*18 + blockIdx.x)*CC + tid] =
                redp[tid] + redp[128+tid] + redp[256+tid] + redp[384+tid];
    }
}

// ---------------- score: smem-restaged coalesced e output -----------------------
#define ESTRIDE 68
#define POOLSZ (128*ESTRIDE + 512 + 16*132)

__global__ __launch_bounds__(256, 2) void score_t()
{
    const int b  = blockIdx.z;
    const int n0 = blockIdx.y * 128;
    const int m0 = blockIdx.x * 128;
    const float* kx = g_kx + (size_t)b*CC*NPIX;
    const float* qx = g_qx + (size_t)b*CC*NPIX;
    unsigned short* eb = g_e + (size_t)b*NPIX*NPIX;
    __shared__ __align__(16) unsigned s_pool[POOLSZ];
    __shared__ float smax[8];
    float* Asf = (float*)s_pool;             // [2][BSZ]
    float* Bsf = Asf + 2*BSZ;                // [2][BSZ]
    const int tid = threadIdx.x, lane = tid & 31, wid = tid >> 5;
    const int wm = wid & 1, wn = wid >> 1;
    const int gid = lane >> 2, t4 = lane & 3;
    const int ak = tid >> 4, aq = tid & 15;
    float acc[4][4][4] = {};
    float4 pa0, pa1, pb0, pb1;
    pa0 = *(const float4*)&kx[(size_t)ak*NPIX + n0 + aq*4];
    pa1 = *(const float4*)&kx[(size_t)ak*NPIX + n0 + 64 + aq*4];
    pb0 = *(const float4*)&qx[(size_t)ak*NPIX + m0 + aq*4];
    pb1 = *(const float4*)&qx[(size_t)ak*NPIX + m0 + 64 + aq*4];
    *(float4*)&Asf[ak*136 + aq*4]      = pa0;
    *(float4*)&Asf[ak*136 + 64 + aq*4] = pa1;
    *(float4*)&Bsf[ak*136 + aq*4]      = pb0;
    *(float4*)&Bsf[ak*136 + 64 + aq*4] = pb1;
    __syncthreads();
    for (int it = 0; it < CC/16; ++it) {
        if (it + 1 < CC/16) {
            int k0 = (it+1)*16;
            pa0 = *(const float4*)&kx[(size_t)(k0+ak)*NPIX + n0 + aq*4];
            pa1 = *(const float4*)&kx[(size_t)(k0+ak)*NPIX + n0 + 64 + aq*4];
            pb0 = *(const float4*)&qx[(size_t)(k0+ak)*NPIX + m0 + aq*4];
            pb1 = *(const float4*)&qx[(size_t)(k0+ak)*NPIX + m0 + 64 + aq*4];
        }
        mma_AB_kn(acc, Asf + (it&1)*BSZ, Bsf + (it&1)*BSZ, wm, wn, lane);
        if (it + 1 < CC/16) {
            int nb = (it+1) & 1;
            *(float4*)&Asf[nb*BSZ + ak*136 + aq*4]      = pa0;
            *(float4*)&Asf[nb*BSZ + ak*136 + 64 + aq*4] = pa1;
            *(float4*)&Bsf[nb*BSZ + ak*136 + aq*4]      = pb0;
            *(float4*)&Bsf[nb*BSZ + ak*136 + 64 + aq*4] = pb1;
        }
        __syncthreads();
    }
    float mx = -1e30f;
#pragma unroll
    for (int mf = 0; mf < 4; ++mf)
#pragma unroll
        for (int nf = 0; nf < 4; ++nf)
#pragma unroll
            for (int v = 0; v < 4; ++v) mx = fmaxf(mx, acc[mf][nf][v]);
#pragma unroll
    for (int o = 16; o; o >>= 1) mx = fmaxf(mx, __shfl_xor_sync(~0u, mx, o));
    if (lane == 0) smax[wid] = mx;
    __syncthreads();
    float lm = smax[0];
#pragma unroll
    for (int j = 1; j < 8; ++j) lm = fmaxf(lm, smax[j]);
    unsigned* esh   = s_pool;                           // 128 x ESTRIDE uints
    float* rowred   = (float*)(s_pool + 128*ESTRIDE);   // 4 x 128
    float* colred   = rowred + 512;                     // 16 x 132
    float rowp[8] = {};
    float colp[8] = {};
#pragma unroll
    for (int mf = 0; mf < 4; ++mf)
#pragma unroll
        for (int h = 0; h < 2; ++h) {
            int nl = wm*64 + mf*16 + gid + h*8;
#pragma unroll
            for (int nf = 0; nf < 4; ++nf) {
                float e0 = __expf(acc[mf][nf][2*h+0] - lm);
                float e1 = __expf(acc[mf][nf][2*h+1] - lm);
                esh[nl*ESTRIDE + wn*16 + nf*4 + t4] = packbf(e0, e1);
                rowp[mf*2+h] += e0 + e1;
                colp[nf*2+0] += e0;
                colp[nf*2+1] += e1;
            }
        }
#pragma unroll
    for (int j = 0; j < 8; ++j) {
        float v = rowp[j];
        v += __shfl_xor_sync(~0u, v, 1);
        v += __shfl_xor_sync(~0u, v, 2);
        if (t4 == 0)
            rowred[wn*128 + wm*64 + (j>>1)*16 + gid + (j&1)*8] = v;
    }
#pragma unroll
    for (int j = 0; j < 8; ++j) {
        int cl = wn*32 + (j>>1)*8 + t4*2 + (j&1);
        colred[(wm*8+gid)*132 + cl] = colp[j];
    }
    __syncthreads();
#pragma unroll
    for (int i = 0; i < 16; ++i) {
        int r = wid*16 + i;
        uint2 v = *(const uint2*)&esh[r*ESTRIDE + lane*2];
        uint2* dst = (uint2*)(eb + (size_t)(n0 + r)*NPIX + m0);
        dst[lane] = v;
    }
    if (tid < 128) {
        float r = rowred[tid] + rowred[128+tid] + rowred[256+tid] + rowred[384+tid];
        g_rpart[((size_t)b*18 + blockIdx.x)*NPIX + n0 + tid] = r;
        float c = 0.f;
#pragma unroll
        for (int i = 0; i < 16; ++i) c += colred[i*132 + tid];
        g_cpart[((size_t)b*18 + blockIdx.y)*NPIX + m0 + tid] = c;
    }
    if (tid == 0) {
        g_tmax[(b*18 + blockIdx.y)*18 + blockIdx.x] = lm;
        atomicMax(&g_bmaxk[b], fkey(lm));
    }
}

// ---------------- merged attention (+inline gate): z=0 -> E_s, z=1 -> E_q -------
__global__ __launch_bounds__(256, 2) void attn_t(float* __restrict__ Es,
                                                 float* __restrict__ Eq,
    const float* __restrict__ gw1, const float* __restrict__ gb1,
    const float* __restrict__ gw2, const float* __restrict__ gb2)
{
    const int z  = blockIdx.z;
    const int b  = blockIdx.y;
    const int x0 = blockIdx.x * 128;       // n0 (z=0) or m0 (z=1)
    const unsigned short* eb = g_e + (size_t)b*NPIX*NPIX;
    const unsigned* vh = (const unsigned*)(z == 0 ? g_vsh : g_vqh)
                       + (size_t)b*CC*(NPIX/2);
    const float* resb = (z == 0 ? g_st : g_qt) + (size_t)b*CC*NPIX;
    const float* pp   = (z == 0 ? g_pools : g_poolq) + (size_t)b*18*CC;
    float* Eb = (z == 0 ? Es : Eq) + (size_t)b*CC*NPIX;
    __shared__ unsigned As[2][ASZ];
    __shared__ unsigned Bs[2][ASZ];
    __shared__ float tmx[18];
    __shared__ int   ordsh[18];
    __shared__ float ratio[18];
    __shared__ float inv_s[128];
    __shared__ float pool_sh[128];
    __shared__ float hsh[8];
    __shared__ float gate_sh[128];
    const int tid = threadIdx.x, lane = tid & 31, wid = tid >> 5;
    const int wm = wid & 1, wn = wid >> 1;
    const int gid = lane >> 2, t4 = lane & 3;
    const int am = tid >> 1, half = tid & 1;
    const float bmax = fdekey(g_bmaxk[b]);
    if (tid < 18)
        tmx[tid] = (z == 0) ? g_tmax[(b*18 + blockIdx.x)*18 + tid]
                            : g_tmax[(b*18 + tid)*18 + blockIdx.x];
    if (tid >= 64 && tid < 192) {
        int i = tid - 64;
        float s = 0.f;
#pragma unroll
        for (int j = 0; j < 18; ++j) s += pp[j*CC + i];
        pool_sh[i] = s * (1.0f/NPIX);
    }
    __syncthreads();
    if (tid < 18) {
        float mine = tmx[tid];
        int rank = 0;
        for (int j = 0; j < 18; ++j) {
            float o = tmx[j];
            rank += (o < mine) || (o == mine && j < tid);
        }
        ordsh[rank] = tid;
    }
    if (tid >= 32 && tid < 64) {
        int l = tid - 32;
        int j = l & 7, seg = l >> 3;
        float h = 0.f;
#pragma unroll
        for (int i = 0; i < 32; ++i)
            h += pool_sh[seg*32 + i] * gw1[j*CC + seg*32 + i];
        h += __shfl_xor_sync(0xffffffffu, h, 8);
        h += __shfl_xor_sync(0xffffffffu, h, 16);
        if (l < 8) hsh[j] = fmaxf(h + gb1[j], 0.f);
    }
    __syncthreads();
    if (tid < 18)
        ratio[tid] = (tid == 0) ? 1.0f : __expf(tmx[ordsh[tid-1]] - tmx[ordsh[tid]]);
    if (tid >= 32 && tid < 160) {
        int i = tid - 32;
        const float* part = (z == 0 ? g_rpart : g_cpart);
        float s = 0.f;
#pragma unroll
        for (int t = 0; t < 18; ++t)
            s += __expf(tmx[t] - bmax) * part[((size_t)b*18 + t)*NPIX + x0 + i];
        inv_s[i] = s;
    }
    if (tid >= 192) {
        int i0 = (tid - 192)*2;
#pragma unroll
        for (int u = 0; u < 2; ++u) {
            int i = i0 + u;
            float zv = gb2[i];
#pragma unroll
            for (int j = 0; j < 8; ++j) zv += hsh[j] * gw2[i*8 + j];
            gate_sh[i] = 1.0f / (1.0f + __expf(-zv));
        }
    }
    __syncthreads();
    if (tid < 128) {
        float slast = __expf(tmx[ordsh[17]] - bmax);
        inv_s[tid] = slast / inv_s[tid];
    }
    float acc[4][4][4] = {};
    const unsigned* arow = vh + (size_t)am*(NPIX/2) + half*8;

    if (z == 0) {
        const unsigned* erow = (const unsigned*)(eb + (size_t)(x0+am)*NPIX) + half*8;
        uint4 pa0, pa1, pb0, pb1;
        {
            int ko2 = ordsh[0]*64;
            pa0 = *(const uint4*)&arow[ko2];  pa1 = *(const uint4*)&arow[ko2+4];
            pb0 = *(const uint4*)&erow[ko2];  pb1 = *(const uint4*)&erow[ko2+4];
        }
        auto store = [&](int buf) {
            unsigned* Ap = &As[buf][am*20];
            unsigned* Bp = &Bs[buf][am*20];
            unsigned ua[8] = {pa0.x,pa0.y,pa0.z,pa0.w, pa1.x,pa1.y,pa1.z,pa1.w};
            unsigned ub[8] = {pb0.x,pb0.y,pb0.z,pb0.w, pb1.x,pb1.y,pb1.z,pb1.w};
#pragma unroll
            for (int i = 0; i < 8; ++i) {
                int c = cpos(half*8 + i);
                Ap[c] = ua[i];
                Bp[c] = ub[i];
            }
        };
        store(0);
        __syncthreads();
        for (int it = 0; it < 72; ++it) {
            if (it + 1 < 72) {
                int nit = it + 1;
                int ko2 = ordsh[nit>>2]*64 + (nit&3)*16;
                pa0 = *(const uint4*)&arow[ko2];  pa1 = *(const uint4*)&arow[ko2+4];
                pb0 = *(const uint4*)&erow[ko2];  pb1 = *(const uint4*)&erow[ko2+4];
            }
            if ((it & 3) == 0 && it) {
                float r = ratio[it>>2];
#pragma unroll
                for (int mf = 0; mf < 4; ++mf)
#pragma unroll
                    for (int nf = 0; nf < 4; ++nf)
#pragma unroll
                        for (int v = 0; v < 4; ++v) acc[mf][nf][v] *= r;
            }
            mma_AB16(acc, As[it & 1], Bs[it & 1], wm, wn, lane);
            if (it + 1 < 72) store((it+1) & 1);
            __syncthreads();
        }
    } else {
        const int np = tid >> 4, mseg = tid & 15;
        const unsigned* ebase = (const unsigned*)eb + x0/2 + mseg*4;
        const int ppos = cpos(np);
        uint4 pa0, pa1, pb0, pb1;
        {
            int k0 = ordsh[0]*128;
            pa0 = *(const uint4*)&arow[ordsh[0]*64];
            pa1 = *(const uint4*)&arow[ordsh[0]*64 + 4];
            pb0 = *(const uint4*)&ebase[(size_t)(k0 + 2*np    )*(NPIX/2)];
            pb1 = *(const uint4*)&ebase[(size_t)(k0 + 2*np + 1)*(NPIX/2)];
        }
        auto store = [&](int buf) {
            unsigned* Ap = &As[buf][am*20];
            unsigned ua[8] = {pa0.x,pa0.y,pa0.z,pa0.w, pa1.x,pa1.y,pa1.z,pa1.w};
#pragma unroll
            for (int i = 0; i < 8; ++i) Ap[cpos(half*8 + i)] = ua[i];
            unsigned u0[4] = {pb0.x, pb0.y, pb0.z, pb0.w};
            unsigned u1[4] = {pb1.x, pb1.y, pb1.z, pb1.w};
#pragma unroll
            for (int jj = 0; jj < 4; ++jj) {
                unsigned q0 = __byte_perm(u0[jj], u1[jj], 0x5410);
                unsigned q1 = __byte_perm(u0[jj], u1[jj], 0x7632);
                int ml = mseg*8 + 2*jj;
                Bs[buf][ml*20 + ppos]     = q0;
                Bs[buf][(ml+1)*20 + ppos] = q1;
            }
        };
        store(0);
        __syncthreads();
        for (int it = 0; it < 72; ++it) {
            if (it + 1 < 72) {
                int nit = it + 1;
                int kt = ordsh[nit>>2];
                int k0 = kt*128 + (nit&3)*32;
                pa0 = *(const uint4*)&arow[kt*64 + (nit&3)*16];
                pa1 = *(const uint4*)&arow[kt*64 + (nit&3)*16 + 4];
                pb0 = *(const uint4*)&ebase[(size_t)(k0 + 2*np    )*(NPIX/2)];
                pb1 = *(const uint4*)&ebase[(size_t)(k0 + 2*np + 1)*(NPIX/2)];
            }
            if ((it & 3) == 0 && it) {
                float r = ratio[it>>2];
#pragma unroll
                for (int mf = 0; mf < 4; ++mf)
#pragma unroll
                    for (int nf = 0; nf < 4; ++nf)
#pragma unroll
                        for (int v = 0; v < 4; ++v) acc[mf][nf][v] *= r;
            }
            mma_AB16(acc, As[it & 1], Bs[it & 1], wm, wn, lane);
            if (it + 1 < 72) store((it+1) & 1);
            __syncthreads();
        }
    }
#pragma unroll
    for (int mf = 0; mf < 4; ++mf)
#pragma unroll
        for (int h = 0; h < 2; ++h) {
            int co = wm*64 + mf*16 + gid + h*8;
            float g = gate_sh[co];
#pragma unroll
            for (int nf = 0; nf < 4; ++nf) {
                int cl = wn*32 + nf*8 + t4*2;
                float2 res = *(const float2*)&resb[(size_t)co*NPIX + x0 + cl];
                float2 r;
                r.x = g*acc[mf][nf][2*h+0]*inv_s[cl]   + res.x;
                r.y = g*acc[mf][nf][2*h+1]*inv_s[cl+1] + res.y;
                *(float2*)&Eb[(size_t)co*NPIX + x0 + cl] = r;
            }
        }
}

// ---------------- 3x3 conv: 512 threads, warp tile 32x32, tf32 ------------------
__global__ __launch_bounds__(512) void conv_t(
    const float* __restrict__ cwr, const float* __restrict__ cg,
    const float* __restrict__ cb, const float* __restrict__ cm,
    const float* __restrict__ cv,
    const float* __restrict__ Eq, const float* __restrict__ Es,
    float* __restrict__ feat)
{
    const int b  = blockIdx.y;
    const int p0 = blockIdx.x * 128;
    const float* Eqb = Eq + (size_t)b*CC*NPIX;
    const float* Esb = Es + (size_t)b*CC*NPIX;
    float* fb = feat + (size_t)b*CC*NPIX;
    __shared__ __align__(16) float As[2][ASZ];
    __shared__ __align__(16) float Bs[2][BSZ];
    const int tid = threadIdx.x, lane = tid & 31, wid = tid >> 5;
    const int wm = wid & 3, wn = wid >> 2;           // 4 x 4 warps
    const int gid = lane >> 2, t4 = lane & 3;
    const int am = tid >> 2, aq = tid & 3;           // A: 1 float4 / thread
    const int bk = tid >> 5, bq = tid & 31;          // B: 4 pixels / thread
    int hh[4], ww[4];
#pragma unroll
    for (int j = 0; j < 4; ++j) {
        int p = p0 + bq*4 + j;
        hh[j] = p / 48; ww[j] = p - hh[j]*48;
    }
    auto loadB = [&](int k0, float4& v) {
        int kap = k0 + bk;
        int ic = kap / 9, kk = kap - ic*9;
        int dh = kk/3 - 1, dw = kk - (kk/3)*3 - 1;
        const float* src = (ic < CC) ? Eqb : Esb;
        const float* sp = src + (size_t)(ic & (CC-1))*NPIX;
        float* vp = (float*)&v;
#pragma unroll
        for (int j = 0; j < 4; ++j) {
            int ih = hh[j] + dh, iw = ww[j] + dw;
            vp[j] = ((unsigned)ih < 48u && (unsigned)iw < 48u)
                  ? sp[ih*48 + iw] : 0.f;
        }
    };
    float acc[2][4][4] = {};
    float4 pa, pb;
    pa = *(const float4*)&cwr[am*2304 + aq*4];
    loadB(0, pb);
    stAraw(As[0], am, aq, pa);
    *(float4*)&Bs[0][bk*136 + bq*4] = tf4(pb);
    __syncthreads();
    for (int it = 0; it < 144; ++it) {
        if (it + 1 < 144) {
            int k0 = (it+1)*16;
            pa = *(const float4*)&cwr[am*2304 + k0 + aq*4];
            loadB(k0, pb);
        }
        mma_AB32(acc, As[it & 1], Bs[it & 1], wm, wn, lane);
        if (it + 1 < 144) {
            int nb = (it+1) & 1;
            stAraw(As[nb], am, aq, pa);
            *(float4*)&Bs[nb][bk*136 + bq*4] = tf4(pb);
        }
        __syncthreads();
    }
#pragma unroll
    for (int mf = 0; mf < 2; ++mf)
#pragma unroll
        for (int h = 0; h < 2; ++h) {
            int o = wm*32 + mf*16 + gid + h*8;
            float sc  = cg[o] * rsqrtf(cv[o] + EPSB);
            float cbv = cb[o] - cm[o]*sc;
#pragma unroll
            for (int nf = 0; nf < 4; ++nf) {
                int cl = wn*32 + nf*8 + t4*2;
                float2 r;
                r.x = fmaxf(acc[mf][nf][2*h+0]*sc + cbv, 0.f);
                r.y = fmaxf(acc[mf][nf][2*h+1]*sc + cbv, 0.f);
                *(float2*)&fb[(size_t)o*NPIX + p0 + cl] = r;
            }
        }
}

// ---------------- host ----------------------------------------------------------
extern "C" void kernel_launch(void* const* d_in, const int* in_sizes, int n_in,
                              void* d_out, int out_size)
{
    (void)in_sizes; (void)n_in; (void)out_size;
    const float* q    = (const float*)d_in[0];
    const float* s    = (const float*)d_in[1];
    const float* tsw  = (const float*)d_in[2];
    const float* tsb  = (const float*)d_in[3];
    const float* bsg  = (const float*)d_in[4];
    const float* bsb  = (const float*)d_in[5];
    const float* bsm  = (const float*)d_in[6];
    const float* bsv  = (const float*)d_in[7];
    const float* tqw  = (const float*)d_in[8];
    const float* tqb  = (const float*)d_in[9];
    const float* bqg  = (const float*)d_in[10];
    const float* bqb  = (const float*)d_in[11];
    const float* bqm  = (const float*)d_in[12];
    const float* bqv  = (const float*)d_in[13];
    const float* vqw  = (const float*)d_in[14];
    const float* vqb  = (const float*)d_in[15];
    const float* vsw  = (const float*)d_in[16];
    const float* vsb  = (const float*)d_in[17];
    const float* keyw = (const float*)d_in[18];
    const float* keyb = (const float*)d_in[19];
    const float* qryw = (const float*)d_in[20];
    const float* qryb = (const float*)d_in[21];
    const float* gw1  = (const float*)d_in[22];
    const float* gb1  = (const float*)d_in[23];
    const float* gw2  = (const float*)d_in[24];
    const float* gb2  = (const float*)d_in[25];
    const float* cw   = (const float*)d_in[26];
    const float* cg   = (const float*)d_in[27];
    const float* cb   = (const float*)d_in[28];
    const float* cm   = (const float*)d_in[29];
    const float* cv   = (const float*)d_in[30];

    float *p_qt, *p_st, *p_kx, *p_qx, *p_pq, *p_ps, *p_cwr;
    unsigned short *p_vqh, *p_vsh;
    cudaGetSymbolAddress((void**)&p_qt,  g_qt);
    cudaGetSymbolAddress((void**)&p_st,  g_st);
    cudaGetSymbolAddress((void**)&p_kx,  g_kx);
    cudaGetSymbolAddress((void**)&p_qx,  g_qx);
    cudaGetSymbolAddress((void**)&p_pq,  g_poolq);
    cudaGetSymbolAddress((void**)&p_ps,  g_pools);
    cudaGetSymbolAddress((void**)&p_cwr, g_cwr);
    cudaGetSymbolAddress((void**)&p_vqh, g_vqh);
    cudaGetSymbolAddress((void**)&p_vsh, g_vsh);

    float* feat = (float*)d_out;
    float* Eq   = feat + (size_t)BATCH*CC*NPIX;
    float* Es   = Eq   + (size_t)BATCH*CC*NPIX;

    prep_cw<<<1152, 256>>>(cw, p_cwr);

    // trans pair: z=0 -> q', z=1 -> s'
    {
        GemmJobs jt = {};
        jt.j[0] = { q, tqw, tqb, bqg, bqb, bqm, bqv, p_qt, 0, p_pq, 0 };
        jt.j[1] = { s, tsw, tsb, bsg, bsb, bsm, bsv, p_st, 0, p_ps, 0 };
        gemm_wx_t<<<dim3(18, BATCH, 2), 256>>>(jt, CIN);
    }
    // projection quad: v_q(bf16), q_x(tf32-rounded), v_s(bf16), k_x(tf32-rounded)
    {
        GemmJobs jp = {};
        jp.j[0] = { p_qt, vqw,  vqb,  0, 0, 0, 0, 0,    p_vqh, 0, 0 };
        jp.j[1] = { p_qt, qryw, qryb, 0, 0, 0, 0, p_qx, 0,     0, 1 };
        jp.j[2] = { p_st, vsw,  vsb,  0, 0, 0, 0, 0,    p_vsh, 0, 0 };
        jp.j[3] = { p_st, keyw, keyb, 0, 0, 0, 0, p_kx, 0,     0, 1 };
        gemm_wx_t<<<dim3(18, BATCH, 4), 256>>>(jp, CC);
    }

    score_t<<<dim3(18, 18, BATCH), 256>>>();

    attn_t<<<dim3(18, BATCH, 2), 256>>>(Es, Eq, gw1, gb1, gw2, gb2);

    conv_t<<<dim3(18, BATCH), 512>>>(p_cwr, cg, cb, cm, cv, Eq, Es, feat);
}